// round 16
// baseline (speedup 1.0000x reference)
#include <cuda_runtime.h>
#include <cstdint>

constexpr int BATCH = 128;
constexpr int NODES = 8192;
constexpr int NI    = 6;
constexpr int NE    = 64;
constexpr int BB    = 16;     // batches per thread
constexpr int TPB   = 64;     // 2 threads per node -> 32 nodes per CTA
constexpr int NPC   = TPB / 2;             // nodes per CTA
constexpr int PF    = 4;      // x prefetch depth (register ring, slot = bb&3)
constexpr int XSTRIDE = NODES * NI;        // floats between consecutive batches

using u64 = unsigned long long;

__device__ __forceinline__ u64 pk2(float lo, float hi) {
    u64 r; asm("mov.b64 %0, {%1, %2};" : "=l"(r) : "f"(lo), "f"(hi)); return r;
}
__device__ __forceinline__ void upk2(u64 v, float& lo, float& hi) {
    asm("mov.b64 {%0, %1}, %2;" : "=f"(lo), "=f"(hi) : "l"(v));
}
__device__ __forceinline__ u64 fma2(u64 a, u64 b, u64 c) {
    u64 d; asm("fma.rn.f32x2 %0, %1, %2, %3;" : "=l"(d) : "l"(a), "l"(b), "l"(c)); return d;
}
__device__ __forceinline__ u64 sub2(u64 a, u64 b) {
    u64 d; asm("sub.rn.f32x2 %0, %1, %2;" : "=l"(d) : "l"(a), "l"(b)); return d;
}

// out[b,n] = 6-D multilinear interp of tables[n,:] at clip(x[b,n,:], 0, 1).
// R16: LANE-PAIR SPLIT along bit5. Thread h=tid&1 owns table half 32h..32h+31,
// with bit4 packed into the f32x2 lanes (was bit5). Coefficient registers drop
// 64 -> 32, removing the chronic spills (regs pinned at 128 since R10). Both
// lanes of a pair load the same 24B of x (same sectors: no extra DRAM), bit5
// is combined with one shfl_xor, even lane stores. launch_bounds(64,10) ->
// 20 resident warps/SM (was 13.8) across 2048 CTAs.
__global__ void __launch_bounds__(TPB, 10)
lut_kernel(const float* __restrict__ x,
           const float* __restrict__ tables,
           float* __restrict__ out)
{
    __shared__ float tbl[NPC * NE];          // 8 KB static

    const int tid  = threadIdx.x;
    const int h    = tid & 1;                // bit5 half owned by this thread
    const int r    = tid >> 1;               // node index within CTA
    const int n0   = blockIdx.x * NPC;       // first node of this block
    const int b0   = blockIdx.y * BB;        // first batch of this block
    const int node = n0 + r;

    const float* xt = x + ((size_t)b0 * NODES + node) * NI;

    // ---- kick off x prefetch for batches 0..PF-1 FIRST (overlaps table stage) ----
    // Pair lanes load identical 24B: same 32B sectors -> no added DRAM/L1 traffic.
    float2 buf[PF][3];
    #pragma unroll
    for (int s = 0; s < PF; s++) {
        const float* p = xt + (size_t)s * XSTRIDE;
        buf[s][0] = *(const float2*)(p + 0);
        buf[s][1] = *(const float2*)(p + 2);
        buf[s][2] = *(const float2*)(p + 4);
    }

    // ---- stage this block's 8KB table chunk: coalesced LDG -> +2*row-rotated STS.64 ----
    {
        const float4* tg = (const float4*)(tables + (size_t)n0 * NE);
        #pragma unroll
        for (int j = 0; j < (NPC * NE / 4) / TPB; j++) {    // 8 float4 per thread
            int i = tid + j * TPB;                          // coalesced gmem index
            float4 v = tg[i];
            int row = i >> 4;                               // dest row (0..31)
            int c0  = (i & 15) * 4;                         // first word (even)
            float* rw = tbl + row * NE;
            int w0 = (c0     + 2 * row) & (NE - 1);         // even -> 8B aligned
            int w1 = (c0 + 2 + 2 * row) & (NE - 1);
            *(float2*)(rw + w0) = make_float2(v.x, v.y);
            *(float2*)(rw + w1) = make_float2(v.z, v.w);
        }
    }
    __syncthreads();

    // ---- per-thread packed quad coefficients over bits 0,1 (pairing = bit 4) ----
    // This thread's entries: e = 32h + 16*b4 + 4*m + (bits 0,1), m = bit2 + 2*bit3.
    // Packed quad m: lo lane = b4=0 group, hi lane = b4=1 group.
    //   val = a + x0*b + x1*c + x0*x1*d
    u64 Aq[4], Bq[4], Cq[4], Dq[4];
    {
        const float* tr  = tbl + (size_t)r * NE;
        const int    rot = (2 * r) & (NE - 1);              // even: float2 pairs intact
        const int    eb  = 32 * h;                          // half base
        #pragma unroll
        for (int m = 0; m < 4; m++) {
            float2 l01 = *(const float2*)(tr + ((eb + 4*m      + rot) & (NE - 1)));
            float2 l23 = *(const float2*)(tr + ((eb + 4*m + 2  + rot) & (NE - 1)));
            float2 h01 = *(const float2*)(tr + ((eb + 4*m + 16 + rot) & (NE - 1)));
            float2 h23 = *(const float2*)(tr + ((eb + 4*m + 18 + rot) & (NE - 1)));
            float lb = l01.y - l01.x, hb = h01.y - h01.x;
            Aq[m] = pk2(l01.x, h01.x);
            Bq[m] = pk2(lb, hb);
            Cq[m] = pk2(l23.x - l01.x, h23.x - h01.x);
            Dq[m] = pk2((l23.y - l23.x) - lb, (h23.y - h23.x) - hb);
        }
    }

    // ---- fold body: returns this half's 5-bit-folded result, then bit5 via shfl ----
    auto fold = [&](float2 q0, float2 q1, float2 q2) -> float {
        float c0 = __saturatef(q0.x), c1 = __saturatef(q0.y);
        float c2 = __saturatef(q1.x), c3 = __saturatef(q1.y);
        float c4 = __saturatef(q2.x), c5 = __saturatef(q2.y);
        float c01 = c0 * c1;
        u64 x0  = pk2(c0,  c0), x1 = pk2(c1, c1), x01 = pk2(c01, c01);
        u64 x2  = pk2(c2,  c2), x3 = pk2(c3, c3);

        // bits 0,1: 3 FFMA2 per packed quad, 4 independent chains
        u64 W[4];
        #pragma unroll
        for (int m = 0; m < 4; m++)
            W[m] = fma2(x01, Dq[m], fma2(x1, Cq[m], fma2(x0, Bq[m], Aq[m])));

        // bit 2, bit 3: packed difference-form lerps (lanes still = bit4)
        W[0] = fma2(x2, sub2(W[1], W[0]), W[0]);
        W[1] = fma2(x2, sub2(W[3], W[2]), W[2]);
        W[0] = fma2(x3, sub2(W[1], W[0]), W[0]);

        // bit 4: scalar lerp across the packed halves
        float lo, hi; upk2(W[0], lo, hi);
        float rr = fmaf(c4, hi - lo, lo);

        // bit 5: partner lane holds the other half. Even lane (h=0) has r0,
        // partner value p is r1 -> final = r0 + c5*(r1-r0). (Odd lane's value
        // is unused; only even lanes store.)
        float p = __shfl_xor_sync(0xffffffffu, rr, 1);
        return fmaf(c5, p - rr, rr);
    };

    float*       op   = out + (size_t)b0 * NODES + node;
    const float* xpre = xt + (size_t)PF * XSTRIDE;

    // ---- mainloop: 12 iters, unroll 4 (slot index bb&3 static), ptr increments ----
    #pragma unroll 4
    for (int bb = 0; bb < BB - PF; bb++) {
        const int s = bb & (PF - 1);
        float2 q0 = buf[s][0];
        float2 q1 = buf[s][1];
        float2 q2 = buf[s][2];

        buf[s][0] = *(const float2*)(xpre + 0);             // refill slot for bb+PF
        buf[s][1] = *(const float2*)(xpre + 2);
        buf[s][2] = *(const float2*)(xpre + 4);
        xpre += XSTRIDE;

        float res = fold(q0, q1, q2);
        if (h == 0) *op = res;                              // even lanes: 64B/warp contiguous
        op += NODES;
    }

    // ---- epilogue: last PF batches, no refill (slots static) ----
    #pragma unroll
    for (int bb = BB - PF; bb < BB; bb++) {
        const int s = bb & (PF - 1);
        float res = fold(buf[s][0], buf[s][1], buf[s][2]);
        if (h == 0) *op = res;
        op += NODES;
    }
}

extern "C" void kernel_launch(void* const* d_in, const int* in_sizes, int n_in,
                              void* d_out, int out_size)
{
    const float* x;
    const float* tables;
    if (in_sizes[0] == BATCH * NODES * NI) {
        x = (const float*)d_in[0]; tables = (const float*)d_in[1];
    } else {
        x = (const float*)d_in[1]; tables = (const float*)d_in[0];
    }
    dim3 grid(NODES / NPC, BATCH / BB);     // 256 x 8 = 2048 CTAs
    lut_kernel<<<grid, TPB>>>(x, tables, (float*)d_out);
}